// round 6
// baseline (speedup 1.0000x reference)
#include <cuda_runtime.h>
#include <math.h>
#include <stdint.h>

#define BB 2048
#define SS 200
#define DD 192
#define H1 64
#define H2 32
#define NT 512
#define KT 32
#define NTILE 6
#define APAD 204     // transposed A-tile row stride (floats), %4==0 for LDS.128
#define SPAD 202     // Ht row stride (floats), even for 8B stores

typedef unsigned long long ull;

// ---- smem layout (floats) ----
#define SM_WEFF 0                       // [192][64] = 12288 (dead after GEMM)
#define SM_ABUF 12288                   // 2*KT*APAD = 13056 ; Ht overlay 64*202=12928
#define SM_QS   (SM_ABUF + 13056)      // 192
#define SM_B1   (SM_QS + 192)          // 64
#define SM_W2   (SM_B1 + 64)           // 2048 [h][k]
#define SM_W3   (SM_W2 + 2048)         // 32
#define SM_B2   (SM_W3 + 32)           // 32
#define SM_SC   (SM_B2 + 32)           // 256
#define SM_WGT  (SM_SC + 256)          // 256
#define SM_RED  (SM_WGT + 256)         // 512
#define SMEM_FLOATS (SM_RED + 512)     // 28736 floats = 114944 B

__device__ __forceinline__ ull pk2(float x) {
    ull r; asm("mov.b64 %0, {%1, %1};" : "=l"(r) : "f"(x)); return r;
}
__device__ __forceinline__ ull pk2p(float x, float y) {
    ull r; asm("mov.b64 %0, {%1, %2};" : "=l"(r) : "f"(x), "f"(y)); return r;
}
__device__ __forceinline__ void fma2(ull& d, ull a, ull b) {
    asm("fma.rn.f32x2 %0, %1, %2, %0;" : "+l"(d) : "l"(a), "l"(b));
}
__device__ __forceinline__ float2 up2(ull v) {
    float2 r; asm("mov.b64 {%0, %1}, %2;" : "=f"(r.x), "=f"(r.y) : "l"(v)); return r;
}

__global__ __launch_bounds__(NT, 1)
void rich_attn_kernel(const float* __restrict__ query,
                      const float* __restrict__ keys,
                      const int*   __restrict__ kmask,
                      const float* __restrict__ W1,
                      const float* __restrict__ b1,
                      const float* __restrict__ a1p,
                      const float* __restrict__ W2,
                      const float* __restrict__ b2,
                      const float* __restrict__ a2p,
                      const float* __restrict__ W3,
                      const float* __restrict__ b3p,
                      float* __restrict__ out)
{
    extern __shared__ float sm[];
    const int tid = threadIdx.x;
    const int b   = blockIdx.x;

    const float a1 = a1p[0];
    const float a2 = a2p[0];
    const float b3 = b3p[0];

    const float* kbase = keys + (size_t)b * SS * DD;

    float* weff  = sm + SM_WEFF;
    float* qs    = sm + SM_QS;
    float* bias1 = sm + SM_B1;
    float* w2s   = sm + SM_W2;
    float* w3s   = sm + SM_W3;
    float* b2s   = sm + SM_B2;
    float* score = sm + SM_SC;
    float* wgt   = sm + SM_WGT;
    float* red   = sm + SM_RED;

    // ================= loader group: tid in [400, 512) =================
    const bool isload = (tid >= 400);
    const int lt = tid - 400;          // 0..111
    float4 lr[15];

    if (isload) {
        // LDG tile 0
        const float* g0 = kbase;
        #pragma unroll
        for (int j = 0; j < 15; j++) {
            int f = lt + 112 * j;
            if (f < 1600) {
                int s = f >> 3, kq = f & 7;
                lr[j] = *reinterpret_cast<const float4*>(g0 + (size_t)s * DD + 4 * kq);
            }
        }
        // STS tile 0 -> buf0
        float* A0 = sm + SM_ABUF;
        #pragma unroll
        for (int j = 0; j < 15; j++) {
            int f = lt + 112 * j;
            if (f < 1600) {
                int s = f >> 3, kq = f & 7, kk = 4 * kq;
                A0[(kk+0)*APAD + s] = lr[j].x; A0[(kk+1)*APAD + s] = lr[j].y;
                A0[(kk+2)*APAD + s] = lr[j].z; A0[(kk+3)*APAD + s] = lr[j].w;
            }
        }
        // LDG tile 1 -> regs
        const float* g1 = kbase + KT;
        #pragma unroll
        for (int j = 0; j < 15; j++) {
            int f = lt + 112 * j;
            if (f < 1600) {
                int s = f >> 3, kq = f & 7;
                lr[j] = *reinterpret_cast<const float4*>(g1 + (size_t)s * DD + 4 * kq);
            }
        }
    }

    // ---- q + small weights (all threads) ----
    if (tid < DD) qs[tid] = query[(size_t)b * DD + tid];
    for (int idx = tid; idx < H1 * H2; idx += NT) w2s[idx] = W2[idx];
    if (tid < H2) { w3s[tid] = W3[tid]; b2s[tid] = b2[tid]; }
    if (tid >= 200 && tid < 256) score[tid] = -INFINITY;
    __syncthreads();   // qs ready

    // ---- weff[i][h] = W1[i,h] + W1[576+i,h] + q_i*W1[384+i,h] (plain layout) ----
    for (int idx = tid; idx < DD * H1; idx += NT) {
        int i = idx >> 6;
        int h = idx & 63;
        weff[idx] = W1[idx] + W1[(576 + i) * H1 + h] + qs[i] * W1[(384 + i) * H1 + h];
    }
    // ---- bias1 ----
    {
        int h = tid & 63;
        int c = tid >> 6;                 // 0..7 chunks of 24
        float acc_ = 0.f;
        int i0 = c * 24;
        #pragma unroll 4
        for (int i = i0; i < i0 + 24; i++)
            acc_ = fmaf(qs[i], W1[(192 + i) * H1 + h] - W1[(576 + i) * H1 + h], acc_);
        red[tid] = acc_;
    }
    __syncthreads();
    if (tid < H1) {
        float acc_ = b1[tid];
        #pragma unroll
        for (int c = 0; c < 8; c++) acc_ += red[tid + 64 * c];
        bias1[tid] = acc_;
    }
    __syncthreads();   // weff + bias1 + buf0 ready

    // ================= GEMM: 400 comp threads, 2 k-slices ==============
    // thread -> (ks, sg, hg): slice ks handles k in [ks*16, ks*16+16) of each tile
    const bool comp = (tid < 400);
    const int ks  = (tid >= 200) ? 1 : 0;
    const int T2  = tid - ks * 200;
    const int sg  = T2 >> 3;           // 0..24
    const int hg  = T2 & 7;            // 0..7
    const int s0  = sg * 8;
    const int h0  = hg * 8;

    ull acc[4][8];                      // [s-pair][h]
    if (comp) {
        if (ks == 0) {
            #pragma unroll
            for (int h = 0; h < 8; h++) {
                ull bi = pk2(bias1[h0 + h]);
                #pragma unroll
                for (int p = 0; p < 4; p++) acc[p][h] = bi;
            }
        } else {
            #pragma unroll
            for (int p = 0; p < 4; p++)
                #pragma unroll
                for (int h = 0; h < 8; h++) acc[p][h] = 0ull;
        }
    }

    for (int t = 0; t < NTILE; t++) {
        if (comp) {
            const float* At = sm + SM_ABUF + (t & 1) * KT * APAD + (ks * 16) * APAD + s0;
            const float* Bt = weff + (t * KT + ks * 16) * H1 + h0;
            #pragma unroll 8
            for (int kk = 0; kk < 16; kk++) {
                ulonglong2 a01 = *reinterpret_cast<const ulonglong2*>(At + kk * APAD);
                ulonglong2 a23 = *reinterpret_cast<const ulonglong2*>(At + kk * APAD + 4);
                float4 bv0 = *reinterpret_cast<const float4*>(Bt + kk * H1);
                float4 bv1 = *reinterpret_cast<const float4*>(Bt + kk * H1 + 4);
                ull ap[4] = {a01.x, a01.y, a23.x, a23.y};
                ull bd[8] = {pk2(bv0.x), pk2(bv0.y), pk2(bv0.z), pk2(bv0.w),
                             pk2(bv1.x), pk2(bv1.y), pk2(bv1.z), pk2(bv1.w)};
                #pragma unroll
                for (int p = 0; p < 4; p++) {
                    #pragma unroll
                    for (int h = 0; h < 8; h++)
                        fma2(acc[p][h], ap[p], bd[h]);
                }
            }
        } else if (isload) {
            if (t + 1 < NTILE) {
                float* A0 = sm + SM_ABUF + ((t + 1) & 1) * KT * APAD;
                #pragma unroll
                for (int j = 0; j < 15; j++) {
                    int f = lt + 112 * j;
                    if (f < 1600) {
                        int s = f >> 3, kq = f & 7, kk = 4 * kq;
                        A0[(kk+0)*APAD + s] = lr[j].x; A0[(kk+1)*APAD + s] = lr[j].y;
                        A0[(kk+2)*APAD + s] = lr[j].z; A0[(kk+3)*APAD + s] = lr[j].w;
                    }
                }
            }
            if (t + 2 < NTILE) {
                const float* g = kbase + (t + 2) * KT;
                #pragma unroll
                for (int j = 0; j < 15; j++) {
                    int f = lt + 112 * j;
                    if (f < 1600) {
                        int s = f >> 3, kq = f & 7;
                        lr[j] = *reinterpret_cast<const float4*>(g + (size_t)s * DD + 4 * kq);
                    }
                }
            }
        }
        __syncthreads();
    }

    // ============ combine k-slices + prelu1 -> Ht[h][s] (overlay Abuf) ============
    float* Ht = sm + SM_ABUF;          // [64][SPAD]
    if (comp && ks == 1) {
        // slice1 stores raw partials
        #pragma unroll
        for (int p = 0; p < 4; p++)
            #pragma unroll
            for (int h = 0; h < 8; h++)
                *reinterpret_cast<ull*>(Ht + (h0 + h) * SPAD + s0 + 2 * p) = acc[p][h];
    }
    __syncthreads();
    if (comp && ks == 0) {
        #pragma unroll
        for (int p = 0; p < 4; p++) {
            #pragma unroll
            for (int h = 0; h < 8; h++) {
                ull part = *reinterpret_cast<ull*>(Ht + (h0 + h) * SPAD + s0 + 2 * p);
                float2 aa = up2(acc[p][h]);
                float2 bb = up2(part);
                float v0 = aa.x + bb.x;
                float v1 = aa.y + bb.y;
                v0 = (v0 >= 0.f) ? v0 : a1 * v0;
                v1 = (v1 >= 0.f) ? v1 : a1 * v1;
                *reinterpret_cast<ull*>(Ht + (h0 + h) * SPAD + s0 + 2 * p) = pk2p(v0, v1);
            }
        }
    }
    __syncthreads();

    // ============ layers 2+3 per s ============
    if (tid < SS) {
        const int s = tid;
        ull acc2[16];
        {
            const ulonglong2* bp = reinterpret_cast<const ulonglong2*>(b2s);
            #pragma unroll
            for (int j = 0; j < 8; j++) { acc2[2*j] = bp[j].x; acc2[2*j+1] = bp[j].y; }
        }
        #pragma unroll 8
        for (int h = 0; h < H1; h++) {
            ull xx = pk2(Ht[h * SPAD + s]);
            const ulonglong2* wr = reinterpret_cast<const ulonglong2*>(w2s + h * H2);
            #pragma unroll
            for (int j4 = 0; j4 < 8; j4++) {
                ulonglong2 wv = wr[j4];
                fma2(acc2[2*j4],   xx, wv.x);
                fma2(acc2[2*j4+1], xx, wv.y);
            }
        }
        float sc = b3;
        #pragma unroll
        for (int j = 0; j < 16; j++) {
            float2 p = up2(acc2[j]);
            float v0 = (p.x >= 0.f) ? p.x : a2 * p.x;
            float v1 = (p.y >= 0.f) ? p.y : a2 * p.y;
            sc = fmaf(v0, w3s[2*j], sc);
            sc = fmaf(v1, w3s[2*j + 1], sc);
        }
        int mv = kmask[(size_t)b * SS + s];
        score[s] = mv ? sc : -INFINITY;
    }
    __syncthreads();

    // ============ softmax over 256-padded score ============
    if (tid < 256) red[tid] = score[tid];
    __syncthreads();
    #pragma unroll
    for (int off = 128; off > 0; off >>= 1) {
        if (tid < off) red[tid] = fmaxf(red[tid], red[tid + off]);
        __syncthreads();
    }
    const float m = red[0];
    __syncthreads();

    float e = 0.f;
    if (tid < SS && m > -INFINITY) {
        float svv = score[tid];
        e = (svv > -INFINITY) ? expf(svv - m) : 0.f;
    }
    if (tid < 256) red[tid] = e;
    __syncthreads();
    #pragma unroll
    for (int off = 128; off > 0; off >>= 1) {
        if (tid < off) red[tid] += red[tid + off];
        __syncthreads();
    }
    const float ssum = red[0];
    __syncthreads();
    const float inv = (ssum > 0.f) ? (1.f / ssum) : 0.f;

    if (tid < 256) {
        float wv = e * inv;
        wgt[tid] = wv;
        if (tid < SS) out[(size_t)BB * DD + (size_t)b * SS + tid] = wv;
    }
    __syncthreads();

    // ============ weighted sum: out[b,d] = sum_s wgt[s]*keys[b,s,d] ============
    if (tid < 2 * DD) {
        int half = (tid >= DD);
        int d = tid - half * DD;
        const float* kb = kbase + (size_t)(half * 100) * DD + d;
        const float* wp = wgt + half * 100;
        float accw = 0.f;
        #pragma unroll 5
        for (int si = 0; si < 100; si++)
            accw = fmaf(wp[si], kb[(size_t)si * DD], accw);
        red[tid] = accw;
    }
    __syncthreads();
    if (tid < DD) out[(size_t)b * DD + tid] = red[tid] + red[tid + DD];
}

extern "C" void kernel_launch(void* const* d_in, const int* in_sizes, int n_in,
                              void* d_out, int out_size)
{
    const float* query = (const float*)d_in[0];
    const float* keys  = (const float*)d_in[1];
    const int*   mask  = (const int*)  d_in[2];
    const float* W1    = (const float*)d_in[3];
    const float* b1    = (const float*)d_in[4];
    const float* a1    = (const float*)d_in[5];
    const float* W2    = (const float*)d_in[6];
    const float* b2    = (const float*)d_in[7];
    const float* a2    = (const float*)d_in[8];
    const float* W3    = (const float*)d_in[9];
    const float* b3    = (const float*)d_in[10];
    float* out = (float*)d_out;

    static bool attr_set = false;
    if (!attr_set) {
        cudaFuncSetAttribute(rich_attn_kernel,
                             cudaFuncAttributeMaxDynamicSharedMemorySize,
                             SMEM_FLOATS * sizeof(float));
        attr_set = true;
    }

    rich_attn_kernel<<<BB, NT, SMEM_FLOATS * sizeof(float)>>>(
        query, keys, mask, W1, b1, a1, W2, b2, a2, W3, b3, out);
}

// round 7
// speedup vs baseline: 1.3435x; 1.3435x over previous
#include <cuda_runtime.h>
#include <math.h>
#include <stdint.h>

#define BB 2048
#define SS 200
#define DD 192
#define H1 64
#define H2 32
#define NT 256
#define KT 24
#define NTILE 8
#define APAD 204     // A-tile k-row stride (floats)
#define SPAD 200     // Ht row stride (even -> 8B aligned pair stores)

typedef unsigned long long ull;

// ---- smem layout (floats) ----
#define SM_WEFF 0                      // 12288 (dead after GEMM; Ht overlay)
#define SM_ABUF 12288                  // 2*KT*APAD = 9792 (dead after GEMM)
#define SM_QS   (SM_ABUF + 9792)       // 192
#define SM_B1   (SM_QS + 192)          // 64
#define SM_W2   (SM_B1 + 64)           // 2048 [h][k]
#define SM_W3   (SM_W2 + 2048)         // 32
#define SM_B2   (SM_W3 + 32)           // 32
#define SM_SC   (SM_B2 + 32)           // 256
#define SM_WGT  (SM_SC + 256)          // 256
#define SM_RED  (SM_WGT + 256)         // 256
#define SMEM_FLOATS (SM_RED + 256)     // 25216 floats = 100864 B  (x2 fits an SM)

__device__ __forceinline__ ull pk2(float x) {
    ull r; asm("mov.b64 %0, {%1, %1};" : "=l"(r) : "f"(x)); return r;
}
__device__ __forceinline__ ull pk2p(float x, float y) {
    ull r; asm("mov.b64 %0, {%1, %2};" : "=l"(r) : "f"(x), "f"(y)); return r;
}
__device__ __forceinline__ void fma2(ull& d, ull a, ull b) {
    asm("fma.rn.f32x2 %0, %1, %2, %0;" : "+l"(d) : "l"(a), "l"(b));
}
__device__ __forceinline__ float2 up2(ull v) {
    float2 r; asm("mov.b64 {%0, %1}, %2;" : "=f"(r.x), "=f"(r.y) : "l"(v)); return r;
}

__global__ __launch_bounds__(NT, 2)
void rich_attn_kernel(const float* __restrict__ query,
                      const float* __restrict__ keys,
                      const int*   __restrict__ kmask,
                      const float* __restrict__ W1,
                      const float* __restrict__ b1,
                      const float* __restrict__ a1p,
                      const float* __restrict__ W2,
                      const float* __restrict__ b2,
                      const float* __restrict__ a2p,
                      const float* __restrict__ W3,
                      const float* __restrict__ b3p,
                      float* __restrict__ out)
{
    extern __shared__ float sm[];
    const int tid = threadIdx.x;
    const int b   = blockIdx.x;

    const float a1 = a1p[0];
    const float a2 = a2p[0];
    const float b3 = b3p[0];

    const float* kbase = keys + (size_t)b * SS * DD;

    float* weff  = sm + SM_WEFF;
    float* qs    = sm + SM_QS;
    float* bias1 = sm + SM_B1;
    float* w2s   = sm + SM_W2;
    float* w3s   = sm + SM_W3;
    float* b2s   = sm + SM_B2;
    float* score = sm + SM_SC;
    float* wgt   = sm + SM_WGT;
    float* red   = sm + SM_RED;

    // ---- loader mapping: per tile 200*KT floats = 1200 float4 ----
    // f in [0,1200): s = f/6, kq = f%6, covers k offsets 4*kq..4*kq+3
    float4 st[5];
    int   sf[5], kf[5];
    #pragma unroll
    for (int j = 0; j < 5; j++) {
        int f = tid + NT * j;
        if (f < 1200) { sf[j] = f / 6; kf[j] = f - 6 * sf[j]; }
        else          { sf[j] = -1; kf[j] = 0; }
    }

    // ---- prologue: LDG tile0 ----
    #pragma unroll
    for (int j = 0; j < 5; j++)
        if (sf[j] >= 0)
            st[j] = *reinterpret_cast<const float4*>(kbase + (size_t)sf[j] * DD + 4 * kf[j]);
    // STS tile0 -> buf0
    {
        float* A0 = sm + SM_ABUF;
        #pragma unroll
        for (int j = 0; j < 5; j++)
            if (sf[j] >= 0) {
                int kk = 4 * kf[j], s = sf[j];
                A0[(kk+0)*APAD + s] = st[j].x; A0[(kk+1)*APAD + s] = st[j].y;
                A0[(kk+2)*APAD + s] = st[j].z; A0[(kk+3)*APAD + s] = st[j].w;
            }
    }
    // LDG tile1 -> regs
    #pragma unroll
    for (int j = 0; j < 5; j++)
        if (sf[j] >= 0)
            st[j] = *reinterpret_cast<const float4*>(kbase + KT + (size_t)sf[j] * DD + 4 * kf[j]);

    // ---- q + small weights ----
    if (tid < DD) qs[tid] = query[(size_t)b * DD + tid];
    for (int idx = tid; idx < H1 * H2; idx += NT) w2s[idx] = W2[idx];
    if (tid < H2) { w3s[tid] = W3[tid]; b2s[tid] = b2[tid]; }
    if (tid >= 200) score[tid] = -INFINITY;
    __syncthreads();   // qs ready, tile0 in smem

    // ---- weff[i][h] (float4 over h): 192*16 h4-groups / 256 = 12 iters ----
    for (int idx = tid; idx < DD * 16; idx += NT) {
        int i  = idx >> 4;
        int h4 = (idx & 15) << 2;
        float  qv = qs[i];
        float4 r0 = *reinterpret_cast<const float4*>(W1 + (size_t)i * H1 + h4);
        float4 r1 = *reinterpret_cast<const float4*>(W1 + (size_t)(384 + i) * H1 + h4);
        float4 r2 = *reinterpret_cast<const float4*>(W1 + (size_t)(576 + i) * H1 + h4);
        float4 v;
        v.x = r0.x + r2.x + qv * r1.x;
        v.y = r0.y + r2.y + qv * r1.y;
        v.z = r0.z + r2.z + qv * r1.z;
        v.w = r0.w + r2.w + qv * r1.w;
        *reinterpret_cast<float4*>(weff + (size_t)i * H1 + h4) = v;
    }
    // ---- bias1 partials ----
    {
        int h = tid & 63;
        int c = tid >> 6;                 // 0..3, chunks of 48
        float acc_ = 0.f;
        int i0 = c * 48;
        #pragma unroll 4
        for (int i = i0; i < i0 + 48; i++)
            acc_ = fmaf(qs[i], W1[(size_t)(192 + i) * H1 + h] - W1[(size_t)(576 + i) * H1 + h], acc_);
        red[tid] = acc_;
    }
    __syncthreads();
    if (tid < H1)
        bias1[tid] = b1[tid] + red[tid] + red[tid + 64] + red[tid + 128] + red[tid + 192];
    __syncthreads();

    // ---- GEMM: 200 comp threads, tile 8s x 8h, s-paired f32x2 ----
    const bool comp = (tid < 200);
    const int sg = tid >> 3;           // 0..24
    const int hg = tid & 7;            // 0..7
    const int s0 = sg * 8;
    const int h0 = hg * 8;

    ull acc[4][8];
    if (comp) {
        #pragma unroll
        for (int h = 0; h < 8; h++) {
            ull bi = pk2(bias1[h0 + h]);
            #pragma unroll
            for (int p = 0; p < 4; p++) acc[p][h] = bi;
        }
    }

    for (int t = 0; t < NTILE; t++) {
        if (comp) {
            const float* At = sm + SM_ABUF + (t & 1) * KT * APAD + s0;
            const float* Bt = weff + t * KT * H1 + h0;
            #pragma unroll 6
            for (int kk = 0; kk < KT; kk++) {
                ulonglong2 a01 = *reinterpret_cast<const ulonglong2*>(At + kk * APAD);
                ulonglong2 a23 = *reinterpret_cast<const ulonglong2*>(At + kk * APAD + 4);
                float4 bv0 = *reinterpret_cast<const float4*>(Bt + kk * H1);
                float4 bv1 = *reinterpret_cast<const float4*>(Bt + kk * H1 + 4);
                ull ap[4] = {a01.x, a01.y, a23.x, a23.y};
                ull bd[8] = {pk2(bv0.x), pk2(bv0.y), pk2(bv0.z), pk2(bv0.w),
                             pk2(bv1.x), pk2(bv1.y), pk2(bv1.z), pk2(bv1.w)};
                #pragma unroll
                for (int p = 0; p < 4; p++)
                    #pragma unroll
                    for (int h = 0; h < 8; h++)
                        fma2(acc[p][h], ap[p], bd[h]);
            }
        }
        __syncthreads();   // done reading buf[t&1]'s sibling? (buf[(t+1)&1] free)

        if (t + 1 < NTILE) {
            float* A0 = sm + SM_ABUF + ((t + 1) & 1) * KT * APAD;
            #pragma unroll
            for (int j = 0; j < 5; j++)
                if (sf[j] >= 0) {
                    int kk = 4 * kf[j], s = sf[j];
                    A0[(kk+0)*APAD + s] = st[j].x; A0[(kk+1)*APAD + s] = st[j].y;
                    A0[(kk+2)*APAD + s] = st[j].z; A0[(kk+3)*APAD + s] = st[j].w;
                }
            if (t + 2 < NTILE) {
                const float* g = kbase + (t + 2) * KT;
                #pragma unroll
                for (int j = 0; j < 5; j++)
                    if (sf[j] >= 0)
                        st[j] = *reinterpret_cast<const float4*>(g + (size_t)sf[j] * DD + 4 * kf[j]);
            }
        }
        __syncthreads();   // next buf ready
    }

    // ---- prelu1 -> Ht[h][s] overlaying weff/Abuf (both dead) ----
    float* Ht = sm;   // [64][SPAD] = 12800 floats < 22080
    if (comp) {
        #pragma unroll
        for (int p = 0; p < 4; p++) {
            #pragma unroll
            for (int h = 0; h < 8; h++) {
                float2 v = up2(acc[p][h]);
                float v0 = (v.x >= 0.f) ? v.x : a1 * v.x;
                float v1 = (v.y >= 0.f) ? v.y : a1 * v.y;
                *reinterpret_cast<ull*>(Ht + (h0 + h) * SPAD + s0 + 2 * p) = pk2p(v0, v1);
            }
        }
    }
    __syncthreads();

    // ---- layers 2+3 per s ----
    if (tid < SS) {
        const int s = tid;
        ull acc2[16];
        {
            const ulonglong2* bp = reinterpret_cast<const ulonglong2*>(b2s);
            #pragma unroll
            for (int j = 0; j < 8; j++) { acc2[2*j] = bp[j].x; acc2[2*j+1] = bp[j].y; }
        }
        #pragma unroll 8
        for (int h = 0; h < H1; h++) {
            ull xx = pk2(Ht[h * SPAD + s]);
            const ulonglong2* wr = reinterpret_cast<const ulonglong2*>(w2s + h * H2);
            #pragma unroll
            for (int j4 = 0; j4 < 8; j4++) {
                ulonglong2 wv = wr[j4];
                fma2(acc2[2*j4],   xx, wv.x);
                fma2(acc2[2*j4+1], xx, wv.y);
            }
        }
        float sc = b3;
        #pragma unroll
        for (int j = 0; j < 16; j++) {
            float2 p = up2(acc2[j]);
            float v0 = (p.x >= 0.f) ? p.x : a2 * p.x;
            float v1 = (p.y >= 0.f) ? p.y : a2 * p.y;
            sc = fmaf(v0, w3s[2*j], sc);
            sc = fmaf(v1, w3s[2*j + 1], sc);
        }
        int mv = kmask[(size_t)b * SS + s];
        score[s] = mv ? sc : -INFINITY;
    }
    __syncthreads();

    // ---- softmax over 256-padded score ----
    red[tid] = score[tid];
    __syncthreads();
    #pragma unroll
    for (int off = 128; off > 0; off >>= 1) {
        if (tid < off) red[tid] = fmaxf(red[tid], red[tid + off]);
        __syncthreads();
    }
    const float m = red[0];
    __syncthreads();

    float e = 0.f;
    if (tid < SS && m > -INFINITY) {
        float svv = score[tid];
        e = (svv > -INFINITY) ? expf(svv - m) : 0.f;
    }
    red[tid] = e;
    __syncthreads();
    #pragma unroll
    for (int off = 128; off > 0; off >>= 1) {
        if (tid < off) red[tid] += red[tid + off];
        __syncthreads();
    }
    const float ssum = red[0];
    __syncthreads();
    const float inv = (ssum > 0.f) ? (1.f / ssum) : 0.f;

    {
        float wv = e * inv;
        wgt[tid] = wv;
        if (tid < SS) out[(size_t)BB * DD + (size_t)b * SS + tid] = wv;
    }
    __syncthreads();

    // ---- weighted sum: out[b,d] = sum_s wgt[s]*keys[b,s,d] ----
    if (tid < DD) {
        const float* kb = kbase + tid;
        float accw = 0.f;
        #pragma unroll 8
        for (int si = 0; si < SS; si++)
            accw = fmaf(wgt[si], kb[(size_t)si * DD], accw);
        out[(size_t)b * DD + tid] = accw;
    }
}

extern "C" void kernel_launch(void* const* d_in, const int* in_sizes, int n_in,
                              void* d_out, int out_size)
{
    const float* query = (const float*)d_in[0];
    const float* keys  = (const float*)d_in[1];
    const int*   mask  = (const int*)  d_in[2];
    const float* W1    = (const float*)d_in[3];
    const float* b1    = (const float*)d_in[4];
    const float* a1    = (const float*)d_in[5];
    const float* W2    = (const float*)d_in[6];
    const float* b2    = (const float*)d_in[7];
    const float* a2    = (const float*)d_in[8];
    const float* W3    = (const float*)d_in[9];
    const float* b3    = (const float*)d_in[10];
    float* out = (float*)d_out;

    static bool attr_set = false;
    if (!attr_set) {
        cudaFuncSetAttribute(rich_attn_kernel,
                             cudaFuncAttributeMaxDynamicSharedMemorySize,
                             SMEM_FLOATS * sizeof(float));
        attr_set = true;
    }

    rich_attn_kernel<<<BB, NT, SMEM_FLOATS * sizeof(float)>>>(
        query, keys, mask, W1, b1, a1, W2, b2, a2, W3, b3, out);
}